// round 5
// baseline (speedup 1.0000x reference)
#include <cuda_runtime.h>
#include <math.h>
#include <stdint.h>

#define B 4
#define S 2048
#define E 1024
#define D 512
#define M_TOT (B * S)

// Scratch
__device__ float g_Q[B * S * D];
__device__ float g_K[B * S * D];
__device__ float g_V[B * S * D];
__device__ float g_Vt[B * D * S];
__device__ float g_WT[3 * E * D];
__device__ float g_P[(size_t)B * S * S];
__device__ float g_sum[B * S];

#define APAD 36
#define A_STAGE (128 * APAD)       // 4608 floats = 18432 B per operand-stage
#define SMEM_BYTES (4 * A_STAGE * 4)  // 73728 B: [A s0][A s1][B s0][B s1]

__device__ __forceinline__ uint32_t f2tf32(float x) {
    uint32_t r;
    asm("cvt.rna.tf32.f32 %0, %1;" : "=r"(r) : "f"(x));
    return r;
}
__device__ __forceinline__ void mma_tf32(float d[4], const uint32_t a[4], const uint32_t b[2]) {
    asm volatile(
        "mma.sync.aligned.m16n8k8.row.col.f32.tf32.tf32.f32 "
        "{%0,%1,%2,%3}, {%4,%5,%6,%7}, {%8,%9}, {%0,%1,%2,%3};\n"
        : "+f"(d[0]), "+f"(d[1]), "+f"(d[2]), "+f"(d[3])
        : "r"(a[0]), "r"(a[1]), "r"(a[2]), "r"(a[3]), "r"(b[0]), "r"(b[1]));
}
__device__ __forceinline__ void ldsm4(uint32_t& r0, uint32_t& r1, uint32_t& r2, uint32_t& r3,
                                      uint32_t addr) {
    asm volatile("ldmatrix.sync.aligned.m8n8.x4.shared.b16 {%0,%1,%2,%3}, [%4];"
                 : "=r"(r0), "=r"(r1), "=r"(r2), "=r"(r3) : "r"(addr));
}
__device__ __forceinline__ void cpa16(uint32_t dst, const float* src) {
    asm volatile("cp.async.cg.shared.global [%0], [%1], 16;" :: "r"(dst), "l"(src));
}
__device__ __forceinline__ void cpa_commit() { asm volatile("cp.async.commit_group;"); }
__device__ __forceinline__ void cpa_wait1() { asm volatile("cp.async.wait_group 1;"); }
__device__ __forceinline__ void cpa_wait0() { asm volatile("cp.async.wait_group 0;"); }

// ---------------------------------------------------------------------------
// Unified dual-ldmatrix TF32 GEMM mainloop.
// C[128,128] += A[128, 32T] * B[128, 32T]^T, both operands k-major.
// CVT_A: round A fragments to tf32 in-loop (only needed when A = raw input X).
// ---------------------------------------------------------------------------
template <bool CVT_A>
__device__ __forceinline__ void mma_gemm(const float* Ag, int lda,
                                         const float* Bg, int ldb,
                                         int T, float acc[4][4][4])
{
    extern __shared__ float smem[];
    const uint32_t as_u = (uint32_t)__cvta_generic_to_shared(smem);
    const uint32_t bs_u = as_u + 2u * A_STAGE * 4;

    const int tid = threadIdx.x;
    const int warp = tid >> 5, lane = tid & 31;
    const int sub = lane >> 3, li = lane & 7;
    const int wm = (warp >> 2) * 64, wn = (warp & 3) * 32;
    const int ar = tid >> 3, ac = (tid & 7) * 4;

    int a_off[4], b_off[2];
#pragma unroll
    for (int mi = 0; mi < 4; mi++)
        a_off[mi] = (wm + mi * 16 + (sub & 1) * 8 + li) * APAD + (sub >> 1) * 4;
#pragma unroll
    for (int np = 0; np < 2; np++)
        b_off[np] = (wn + np * 16 + (sub >> 1) * 8 + li) * APAD + (sub & 1) * 4;

#pragma unroll
    for (int mi = 0; mi < 4; mi++)
#pragma unroll
        for (int ni = 0; ni < 4; ni++)
#pragma unroll
            for (int r = 0; r < 4; r++) acc[mi][ni][r] = 0.f;

    auto load_stage = [&](int st, int k0) {
#pragma unroll
        for (int it = 0; it < 4; it++) {
            int row = ar + it * 32;
            cpa16(as_u + (uint32_t)(st * A_STAGE + row * APAD + ac) * 4,
                  Ag + (size_t)row * lda + k0 + ac);
            cpa16(bs_u + (uint32_t)(st * A_STAGE + row * APAD + ac) * 4,
                  Bg + (size_t)row * ldb + k0 + ac);
        }
        cpa_commit();
    };

    load_stage(0, 0);
    int s = 0;
    for (int t = 0; t < T; t++, s ^= 1) {
        if (t + 1 < T) { load_stage(s ^ 1, (t + 1) * 32); cpa_wait1(); }
        else           { cpa_wait0(); }
        __syncthreads();

#pragma unroll
        for (int ks = 0; ks < 32; ks += 8) {
            uint32_t af[4][4];
#pragma unroll
            for (int mi = 0; mi < 4; mi++) {
                ldsm4(af[mi][0], af[mi][1], af[mi][2], af[mi][3],
                      as_u + (uint32_t)(s * A_STAGE + a_off[mi] + ks) * 4);
                if (CVT_A) {
#pragma unroll
                    for (int r = 0; r < 4; r++)
                        af[mi][r] = f2tf32(__uint_as_float(af[mi][r]));
                }
            }
            uint32_t bf[4][2];
#pragma unroll
            for (int np = 0; np < 2; np++)
                ldsm4(bf[2 * np][0], bf[2 * np][1], bf[2 * np + 1][0], bf[2 * np + 1][1],
                      bs_u + (uint32_t)(s * A_STAGE + b_off[np] + ks) * 4);
#pragma unroll
            for (int mi = 0; mi < 4; mi++)
#pragma unroll
                for (int ni = 0; ni < 4; ni++)
                    mma_tf32(acc[mi][ni], af[mi], bf[ni]);
        }
        __syncthreads();
    }
}

// ---------------------------------------------------------------------------
// Transposes (tf32-rounded outputs).
// ---------------------------------------------------------------------------
__global__ __launch_bounds__(256) void transpose_w(const float* __restrict__ wq,
                                                   const float* __restrict__ wk,
                                                   const float* __restrict__ wv)
{
    __shared__ float t[32][33];
    const int z = blockIdx.z;
    const float* in = (z == 0) ? wq : (z == 1) ? wk : wv;      // [E][D]
    float* out = g_WT + (size_t)z * E * D;                      // [D][E]
    const int r0 = blockIdx.y * 32, c0 = blockIdx.x * 32;
    const int tx = threadIdx.x & 31, ty = threadIdx.x >> 5;
#pragma unroll
    for (int i = ty; i < 32; i += 8)
        t[i][tx] = in[(size_t)(r0 + i) * D + c0 + tx];
    __syncthreads();
#pragma unroll
    for (int i = ty; i < 32; i += 8)
        out[(size_t)(c0 + i) * E + r0 + tx] = __uint_as_float(f2tf32(t[tx][i]));
}

__global__ __launch_bounds__(256) void transpose_v()
{
    __shared__ float t[32][33];
    const int b = blockIdx.z;
    const float* in = g_V + (size_t)b * S * D;    // [S][D]
    float* out = g_Vt + (size_t)b * D * S;        // [D][S]
    const int r0 = blockIdx.y * 32, c0 = blockIdx.x * 32;
    const int tx = threadIdx.x & 31, ty = threadIdx.x >> 5;
#pragma unroll
    for (int i = ty; i < 32; i += 8)
        t[i][tx] = in[(size_t)(r0 + i) * D + c0 + tx];
    __syncthreads();
#pragma unroll
    for (int i = ty; i < 32; i += 8)
        out[(size_t)(c0 + i) * S + r0 + tx] = __uint_as_float(f2tf32(t[tx][i]));
}

// ---------------------------------------------------------------------------
// Kernel 1: QKV projection. grid=(4, 64, 3). Q/K/V = round(X @ W + b)
// ---------------------------------------------------------------------------
__global__ __launch_bounds__(256, 2) void qkv_tc(
    const float* __restrict__ X,
    const float* __restrict__ bq,
    const float* __restrict__ bk,
    const float* __restrict__ bv)
{
    const int z = blockIdx.z;
    const float* bias; float* out;
    if (z == 0)      { bias = bq; out = g_Q; }
    else if (z == 1) { bias = bk; out = g_K; }
    else             { bias = bv; out = g_V; }

    const int m0 = blockIdx.y * 128;
    const int n0 = blockIdx.x * 128;

    float acc[4][4][4];
    mma_gemm<true>(X + (size_t)m0 * E, E,
                   g_WT + (size_t)z * E * D + (size_t)n0 * E, E,
                   E / 32, acc);

    const int warp = threadIdx.x >> 5, lane = threadIdx.x & 31;
    const int g = lane >> 2, tg = lane & 3;
    const int wm = (warp >> 2) * 64, wn = (warp & 3) * 32;
#pragma unroll
    for (int mi = 0; mi < 4; mi++) {
        int row0 = m0 + wm + mi * 16 + g;
#pragma unroll
        for (int ni = 0; ni < 4; ni++) {
            int col = n0 + wn + ni * 8 + 2 * tg;
            float b0 = bias[col], b1 = bias[col + 1];
            float2 v0, v1;
            v0.x = __uint_as_float(f2tf32(acc[mi][ni][0] + b0));
            v0.y = __uint_as_float(f2tf32(acc[mi][ni][1] + b1));
            v1.x = __uint_as_float(f2tf32(acc[mi][ni][2] + b0));
            v1.y = __uint_as_float(f2tf32(acc[mi][ni][3] + b1));
            *(float2*)(out + (size_t)row0 * D + col) = v0;
            *(float2*)(out + (size_t)(row0 + 8) * D + col) = v1;
        }
    }
}

// ---------------------------------------------------------------------------
// Kernel 2: causal scores. grid=(16,16,B), lower-tri only. No masking stored;
// softmax only reads j<=i and zero-fills the tile tail.
// ---------------------------------------------------------------------------
__global__ __launch_bounds__(256, 2) void scores_tc()
{
    const int nt = blockIdx.x, mt = blockIdx.y;
    if (nt > mt) return;
    const int b = blockIdx.z;

    const int m0 = mt * 128, n0 = nt * 128;

    float acc[4][4][4];
    mma_gemm<false>(g_Q + (size_t)b * S * D + (size_t)m0 * D, D,
                    g_K + (size_t)b * S * D + (size_t)n0 * D, D,
                    D / 32, acc);

    float* P = g_P + (size_t)b * S * S;
    const float scale = rsqrtf((float)D);
    const int warp = threadIdx.x >> 5, lane = threadIdx.x & 31;
    const int g = lane >> 2, tg = lane & 3;
    const int wm = (warp >> 2) * 64, wn = (warp & 3) * 32;
#pragma unroll
    for (int mi = 0; mi < 4; mi++) {
        int gi0 = m0 + wm + mi * 16 + g;
#pragma unroll
        for (int ni = 0; ni < 4; ni++) {
            int gj = n0 + wn + ni * 8 + 2 * tg;
            float2 v0 = {acc[mi][ni][0] * scale, acc[mi][ni][1] * scale};
            float2 v1 = {acc[mi][ni][2] * scale, acc[mi][ni][3] * scale};
            *(float2*)(P + (size_t)gi0 * S + gj) = v0;
            *(float2*)(P + (size_t)(gi0 + 8) * S + gj) = v1;
        }
    }
}

// ---------------------------------------------------------------------------
// Kernel 3: softmax, warp-per-row. Stores tf32-rounded unnormalized exp +
// row sums; zero-fills (i, Jend). grid=(S/8, B)
// ---------------------------------------------------------------------------
__global__ __launch_bounds__(256) void softmax_w()
{
    const int warp = threadIdx.x >> 5, lane = threadIdx.x & 31;
    const int i = blockIdx.x * 8 + warp;
    const int b = blockIdx.y;
    float* row = g_P + ((size_t)b * S + i) * S;
    const int Jend = ((i >> 7) + 1) << 7;

    float m = -INFINITY;
    for (int j0 = lane * 4; j0 < Jend; j0 += 128) {
        float4 v = *(const float4*)(row + j0);
        if (j0 + 3 <= i) {
            m = fmaxf(m, fmaxf(fmaxf(v.x, v.y), fmaxf(v.z, v.w)));
        } else {
            if (j0     <= i) m = fmaxf(m, v.x);
            if (j0 + 1 <= i) m = fmaxf(m, v.y);
            if (j0 + 2 <= i) m = fmaxf(m, v.z);
        }
    }
#pragma unroll
    for (int o = 16; o > 0; o >>= 1) m = fmaxf(m, __shfl_xor_sync(0xffffffffu, m, o));

    float sum = 0.f;
    for (int j0 = lane * 4; j0 < Jend; j0 += 128) {
        float4 v = *(const float4*)(row + j0);
        float4 e;
        e.x = (j0     <= i) ? __uint_as_float(f2tf32(__expf(v.x - m))) : 0.f;
        e.y = (j0 + 1 <= i) ? __uint_as_float(f2tf32(__expf(v.y - m))) : 0.f;
        e.z = (j0 + 2 <= i) ? __uint_as_float(f2tf32(__expf(v.z - m))) : 0.f;
        e.w = (j0 + 3 <= i) ? __uint_as_float(f2tf32(__expf(v.w - m))) : 0.f;
        sum += (e.x + e.y) + (e.z + e.w);
        *(float4*)(row + j0) = e;
    }
#pragma unroll
    for (int o = 16; o > 0; o >>= 1) sum += __shfl_xor_sync(0xffffffffu, sum, o);
    if (lane == 0) g_sum[b * S + i] = sum;
}

// ---------------------------------------------------------------------------
// Kernel 4: O = P @ Vt^T, causal truncation, normalize in epilogue.
// grid=(4, 16, B)
// ---------------------------------------------------------------------------
__global__ __launch_bounds__(256, 2) void pv_tc(float* __restrict__ outp)
{
    const int nt = blockIdx.x, mt = blockIdx.y, b = blockIdx.z;
    const int m0 = mt * 128, n0 = nt * 128;

    float acc[4][4][4];
    mma_gemm<false>(g_P + (size_t)b * S * S + (size_t)m0 * S, S,
                    g_Vt + (size_t)b * D * S + (size_t)n0 * S, S,
                    (mt + 1) * 4, acc);

    float* O = outp + (size_t)b * S * D;
    const int warp = threadIdx.x >> 5, lane = threadIdx.x & 31;
    const int g = lane >> 2, tg = lane & 3;
    const int wm = (warp >> 2) * 64, wn = (warp & 3) * 32;
#pragma unroll
    for (int mi = 0; mi < 4; mi++) {
        int row0 = m0 + wm + mi * 16 + g;
        float inv0 = 1.f / g_sum[b * S + row0];
        float inv1 = 1.f / g_sum[b * S + row0 + 8];
#pragma unroll
        for (int ni = 0; ni < 4; ni++) {
            int col = n0 + wn + ni * 8 + 2 * tg;
            float2 v0 = {acc[mi][ni][0] * inv0, acc[mi][ni][1] * inv0};
            float2 v1 = {acc[mi][ni][2] * inv1, acc[mi][ni][3] * inv1};
            *(float2*)(O + (size_t)row0 * D + col) = v0;
            *(float2*)(O + (size_t)(row0 + 8) * D + col) = v1;
        }
    }
}

// ---------------------------------------------------------------------------
extern "C" void kernel_launch(void* const* d_in, const int* in_sizes, int n_in,
                              void* d_out, int out_size)
{
    const float* x  = (const float*)d_in[0];
    const float* wq = (const float*)d_in[1];
    const float* bq = (const float*)d_in[2];
    const float* wk = (const float*)d_in[3];
    const float* bk = (const float*)d_in[4];
    const float* wv = (const float*)d_in[5];
    const float* bv = (const float*)d_in[6];
    float* out = (float*)d_out;

    cudaFuncSetAttribute(qkv_tc,    cudaFuncAttributeMaxDynamicSharedMemorySize, SMEM_BYTES);
    cudaFuncSetAttribute(scores_tc, cudaFuncAttributeMaxDynamicSharedMemorySize, SMEM_BYTES);
    cudaFuncSetAttribute(pv_tc,     cudaFuncAttributeMaxDynamicSharedMemorySize, SMEM_BYTES);

    dim3 blk(256);

    // 1) Wq/Wk/Wv -> W^T (tf32-rounded)
    transpose_w<<<dim3(D / 32, E / 32, 3), blk>>>(wq, wk, wv);

    // 2) QKV projections
    qkv_tc<<<dim3(D / 128, M_TOT / 128, 3), blk, SMEM_BYTES>>>(x, bq, bk, bv);

    // 3) V -> V^T per batch (tf32-rounded)
    transpose_v<<<dim3(D / 32, S / 32, B), blk>>>();

    // 4) causal scores
    scores_tc<<<dim3(S / 128, S / 128, B), blk, SMEM_BYTES>>>();

    // 5) softmax
    softmax_w<<<dim3(S / 8, B), blk>>>();

    // 6) O = P @ V
    pv_tc<<<dim3(D / 128, S / 128, B), blk, SMEM_BYTES>>>(out);
}

// round 7
// speedup vs baseline: 1.0488x; 1.0488x over previous
#include <cuda_runtime.h>
#include <math.h>
#include <stdint.h>

#define B 4
#define S 2048
#define E 1024
#define D 512
#define M_TOT (B * S)

// Scratch
__device__ float g_Q[B * S * D];
__device__ float g_K[B * S * D];
__device__ float g_Vt[B * D * S];
__device__ float g_WT[3 * E * D];
__device__ float g_Xr[(size_t)M_TOT * E];
__device__ float g_P[(size_t)B * S * S];
__device__ float g_sum[B * S];

#define APAD 36
#define A_STAGE (128 * APAD)          // 4608 floats = 18432 B per operand-stage
#define SMEM_BYTES (4 * A_STAGE * 4)  // 73728 B: [A s0][A s1][B s0][B s1]

__device__ __forceinline__ uint32_t f2tf32(float x) {
    uint32_t r;
    asm("cvt.rna.tf32.f32 %0, %1;" : "=r"(r) : "f"(x));
    return r;
}
__device__ __forceinline__ void mma_tf32(float d[4], const uint32_t a[4], const uint32_t b[2]) {
    asm volatile(
        "mma.sync.aligned.m16n8k8.row.col.f32.tf32.tf32.f32 "
        "{%0,%1,%2,%3}, {%4,%5,%6,%7}, {%8,%9}, {%0,%1,%2,%3};\n"
        : "+f"(d[0]), "+f"(d[1]), "+f"(d[2]), "+f"(d[3])
        : "r"(a[0]), "r"(a[1]), "r"(a[2]), "r"(a[3]), "r"(b[0]), "r"(b[1]));
}
__device__ __forceinline__ void ldsm4(uint32_t& r0, uint32_t& r1, uint32_t& r2, uint32_t& r3,
                                      uint32_t addr) {
    asm volatile("ldmatrix.sync.aligned.m8n8.x4.shared.b16 {%0,%1,%2,%3}, [%4];"
                 : "=r"(r0), "=r"(r1), "=r"(r2), "=r"(r3) : "r"(addr));
}
__device__ __forceinline__ void cpa16(uint32_t dst, const float* src) {
    asm volatile("cp.async.cg.shared.global [%0], [%1], 16;" :: "r"(dst), "l"(src));
}
__device__ __forceinline__ void cpa_commit() { asm volatile("cp.async.commit_group;"); }
__device__ __forceinline__ void cpa_wait0() { asm volatile("cp.async.wait_group 0;"); }

// ---------------------------------------------------------------------------
// Dual-ldmatrix TF32 GEMM mainloop, ONE sync per k-chunk.
// C[128,128] += A[128, 32T] * B[128, 32T]^T, both operands k-major, tf32-ready.
// Per chunk t:  wait0 -> sync -> issue load(t+1) -> compute(t).
// Safety: compute on buf s^1 (iter t-1) precedes the iter-t sync in program
// order for every warp, so overwriting buf s^1 after the sync is race-free.
// ---------------------------------------------------------------------------
__device__ __forceinline__ void mma_gemm(const float* Ag, int lda,
                                         const float* Bg, int ldb,
                                         int T, float acc[4][4][4])
{
    extern __shared__ float smem[];
    const uint32_t as_u = (uint32_t)__cvta_generic_to_shared(smem);
    const uint32_t bs_u = as_u + 2u * A_STAGE * 4;

    const int tid = threadIdx.x;
    const int warp = tid >> 5, lane = tid & 31;
    const int sub = lane >> 3, li = lane & 7;
    const int wm = (warp >> 2) * 64, wn = (warp & 3) * 32;
    const int ar = tid >> 3, ac = (tid & 7) * 4;

    int a_off[4], b_off[2];
#pragma unroll
    for (int mi = 0; mi < 4; mi++)
        a_off[mi] = (wm + mi * 16 + (sub & 1) * 8 + li) * APAD + (sub >> 1) * 4;
#pragma unroll
    for (int np = 0; np < 2; np++)
        b_off[np] = (wn + np * 16 + (sub >> 1) * 8 + li) * APAD + (sub & 1) * 4;

#pragma unroll
    for (int mi = 0; mi < 4; mi++)
#pragma unroll
        for (int ni = 0; ni < 4; ni++)
#pragma unroll
            for (int r = 0; r < 4; r++) acc[mi][ni][r] = 0.f;

    auto load_stage = [&](int st, int k0) {
#pragma unroll
        for (int it = 0; it < 4; it++) {
            int row = ar + it * 32;
            cpa16(as_u + (uint32_t)(st * A_STAGE + row * APAD + ac) * 4,
                  Ag + (size_t)row * lda + k0 + ac);
            cpa16(bs_u + (uint32_t)(st * A_STAGE + row * APAD + ac) * 4,
                  Bg + (size_t)row * ldb + k0 + ac);
        }
        cpa_commit();
    };

    load_stage(0, 0);
    int s = 0;
    for (int t = 0; t < T; t++, s ^= 1) {
        cpa_wait0();
        __syncthreads();
        if (t + 1 < T) load_stage(s ^ 1, (t + 1) * 32);

#pragma unroll
        for (int ks = 0; ks < 32; ks += 8) {
            uint32_t af[4][4];
#pragma unroll
            for (int mi = 0; mi < 4; mi++)
                ldsm4(af[mi][0], af[mi][1], af[mi][2], af[mi][3],
                      as_u + (uint32_t)(s * A_STAGE + a_off[mi] + ks) * 4);
            uint32_t bf[4][2];
#pragma unroll
            for (int np = 0; np < 2; np++)
                ldsm4(bf[2 * np][0], bf[2 * np][1], bf[2 * np + 1][0], bf[2 * np + 1][1],
                      bs_u + (uint32_t)(s * A_STAGE + b_off[np] + ks) * 4);
#pragma unroll
            for (int mi = 0; mi < 4; mi++)
#pragma unroll
                for (int ni = 0; ni < 4; ni++)
                    mma_tf32(acc[mi][ni], af[mi], bf[ni]);
        }
    }
}

// ---------------------------------------------------------------------------
// Pre-passes: round X to tf32; transpose weights (tf32-rounded).
// ---------------------------------------------------------------------------
__global__ __launch_bounds__(256) void round_x(const float* __restrict__ X)
{
    size_t i = ((size_t)blockIdx.x * 256 + threadIdx.x) * 4;
    float4 v = *(const float4*)(X + i);
    v.x = __uint_as_float(f2tf32(v.x));
    v.y = __uint_as_float(f2tf32(v.y));
    v.z = __uint_as_float(f2tf32(v.z));
    v.w = __uint_as_float(f2tf32(v.w));
    *(float4*)(g_Xr + i) = v;
}

__global__ __launch_bounds__(256) void transpose_w(const float* __restrict__ wq,
                                                   const float* __restrict__ wk,
                                                   const float* __restrict__ wv)
{
    __shared__ float t[32][33];
    const int z = blockIdx.z;
    const float* in = (z == 0) ? wq : (z == 1) ? wk : wv;      // [E][D]
    float* out = g_WT + (size_t)z * E * D;                      // [D][E]
    const int r0 = blockIdx.y * 32, c0 = blockIdx.x * 32;
    const int tx = threadIdx.x & 31, ty = threadIdx.x >> 5;
#pragma unroll
    for (int i = ty; i < 32; i += 8)
        t[i][tx] = in[(size_t)(r0 + i) * D + c0 + tx];
    __syncthreads();
#pragma unroll
    for (int i = ty; i < 32; i += 8)
        out[(size_t)(c0 + i) * E + r0 + tx] = __uint_as_float(f2tf32(t[tx][i]));
}

// ---------------------------------------------------------------------------
// Kernel 1: QKV projection. grid=(4, 64, 3). Q/K = round(X@W+b) row-major;
// V is written TRANSPOSED into g_Vt (per-batch [D][S] panes) via smem.
// ---------------------------------------------------------------------------
__global__ __launch_bounds__(256, 2) void qkv_tc(
    const float* __restrict__ bq,
    const float* __restrict__ bk,
    const float* __restrict__ bv)
{
    const int z = blockIdx.z;
    const float* bias = (z == 0) ? bq : (z == 1) ? bk : bv;

    const int m0 = blockIdx.y * 128;
    const int n0 = blockIdx.x * 128;

    float acc[4][4][4];
    mma_gemm(g_Xr + (size_t)m0 * E, E,
             g_WT + (size_t)z * E * D + (size_t)n0 * E, E,
             E / 32, acc);

    const int warp = threadIdx.x >> 5, lane = threadIdx.x & 31;
    const int g = lane >> 2, tg = lane & 3;
    const int wm = (warp >> 2) * 64, wn = (warp & 3) * 32;

    if (z < 2) {
        float* out = (z == 0) ? g_Q : g_K;
#pragma unroll
        for (int mi = 0; mi < 4; mi++) {
            int row0 = m0 + wm + mi * 16 + g;
#pragma unroll
            for (int ni = 0; ni < 4; ni++) {
                int col = n0 + wn + ni * 8 + 2 * tg;
                float b0 = bias[col], b1 = bias[col + 1];
                float2 v0, v1;
                v0.x = __uint_as_float(f2tf32(acc[mi][ni][0] + b0));
                v0.y = __uint_as_float(f2tf32(acc[mi][ni][1] + b1));
                v1.x = __uint_as_float(f2tf32(acc[mi][ni][2] + b0));
                v1.y = __uint_as_float(f2tf32(acc[mi][ni][3] + b1));
                *(float2*)(out + (size_t)row0 * D + col) = v0;
                *(float2*)(out + (size_t)(row0 + 8) * D + col) = v1;
            }
        }
    } else {
        // V: transpose in smem, write g_Vt[b][n0+n][s0..] coalesced.
        // BUGFIX (R6): decompose flattened row m0 into (batch, seq offset).
        const int bb = m0 / S;          // batch index (128-row block never straddles S)
        const int s0 = m0 - bb * S;     // seq offset within batch
        float* Vt = g_Vt + (size_t)bb * D * S;
        extern __shared__ float smem[];
        float (*tsm)[132] = (float(*)[132])smem;   // [n:128][m:128] pad 132
        __syncthreads();                            // mainloop smem reads done
#pragma unroll
        for (int mi = 0; mi < 4; mi++) {
            int lrow = wm + mi * 16 + g;
#pragma unroll
            for (int ni = 0; ni < 4; ni++) {
                int lcol = wn + ni * 8 + 2 * tg;
                float b0 = bias[n0 + lcol], b1 = bias[n0 + lcol + 1];
                tsm[lcol][lrow]         = __uint_as_float(f2tf32(acc[mi][ni][0] + b0));
                tsm[lcol + 1][lrow]     = __uint_as_float(f2tf32(acc[mi][ni][1] + b1));
                tsm[lcol][lrow + 8]     = __uint_as_float(f2tf32(acc[mi][ni][2] + b0));
                tsm[lcol + 1][lrow + 8] = __uint_as_float(f2tf32(acc[mi][ni][3] + b1));
            }
        }
        __syncthreads();
        for (int idx = threadIdx.x; idx < 128 * 32; idx += 256) {
            int n = idx >> 5, c4 = (idx & 31) * 4;
            *(float4*)(Vt + (size_t)(n0 + n) * S + s0 + c4) = *(float4*)&tsm[n][c4];
        }
    }
}

// ---------------------------------------------------------------------------
// Kernel 2: causal scores. grid=(16,16,B), lower-tri only.
// ---------------------------------------------------------------------------
__global__ __launch_bounds__(256, 2) void scores_tc()
{
    const int nt = blockIdx.x, mt = blockIdx.y;
    if (nt > mt) return;
    const int b = blockIdx.z;

    const int m0 = mt * 128, n0 = nt * 128;

    float acc[4][4][4];
    mma_gemm(g_Q + (size_t)b * S * D + (size_t)m0 * D, D,
             g_K + (size_t)b * S * D + (size_t)n0 * D, D,
             D / 32, acc);

    float* P = g_P + (size_t)b * S * S;
    const float scale = rsqrtf((float)D);
    const int warp = threadIdx.x >> 5, lane = threadIdx.x & 31;
    const int g = lane >> 2, tg = lane & 3;
    const int wm = (warp >> 2) * 64, wn = (warp & 3) * 32;
#pragma unroll
    for (int mi = 0; mi < 4; mi++) {
        int gi0 = m0 + wm + mi * 16 + g;
#pragma unroll
        for (int ni = 0; ni < 4; ni++) {
            int gj = n0 + wn + ni * 8 + 2 * tg;
            float2 v0 = {acc[mi][ni][0] * scale, acc[mi][ni][1] * scale};
            float2 v1 = {acc[mi][ni][2] * scale, acc[mi][ni][3] * scale};
            *(float2*)(P + (size_t)gi0 * S + gj) = v0;
            *(float2*)(P + (size_t)(gi0 + 8) * S + gj) = v1;
        }
    }
}

// ---------------------------------------------------------------------------
// Kernel 3: softmax, warp-per-row; tf32-rounded unnormalized exp + row sums.
// ---------------------------------------------------------------------------
__global__ __launch_bounds__(256) void softmax_w()
{
    const int warp = threadIdx.x >> 5, lane = threadIdx.x & 31;
    const int i = blockIdx.x * 8 + warp;
    const int b = blockIdx.y;
    float* row = g_P + ((size_t)b * S + i) * S;
    const int Jend = ((i >> 7) + 1) << 7;

    float m = -INFINITY;
    for (int j0 = lane * 4; j0 < Jend; j0 += 128) {
        float4 v = *(const float4*)(row + j0);
        if (j0 + 3 <= i) {
            m = fmaxf(m, fmaxf(fmaxf(v.x, v.y), fmaxf(v.z, v.w)));
        } else {
            if (j0     <= i) m = fmaxf(m, v.x);
            if (j0 + 1 <= i) m = fmaxf(m, v.y);
            if (j0 + 2 <= i) m = fmaxf(m, v.z);
        }
    }
#pragma unroll
    for (int o = 16; o > 0; o >>= 1) m = fmaxf(m, __shfl_xor_sync(0xffffffffu, m, o));

    float sum = 0.f;
    for (int j0 = lane * 4; j0 < Jend; j0 += 128) {
        float4 v = *(const float4*)(row + j0);
        float4 e;
        e.x = (j0     <= i) ? __uint_as_float(f2tf32(__expf(v.x - m))) : 0.f;
        e.y = (j0 + 1 <= i) ? __uint_as_float(f2tf32(__expf(v.y - m))) : 0.f;
        e.z = (j0 + 2 <= i) ? __uint_as_float(f2tf32(__expf(v.z - m))) : 0.f;
        e.w = (j0 + 3 <= i) ? __uint_as_float(f2tf32(__expf(v.w - m))) : 0.f;
        sum += (e.x + e.y) + (e.z + e.w);
        *(float4*)(row + j0) = e;
    }
#pragma unroll
    for (int o = 16; o > 0; o >>= 1) sum += __shfl_xor_sync(0xffffffffu, sum, o);
    if (lane == 0) g_sum[b * S + i] = sum;
}

// ---------------------------------------------------------------------------
// Kernel 4: O = P @ Vt^T, causal truncation, normalize in epilogue.
// ---------------------------------------------------------------------------
__global__ __launch_bounds__(256, 2) void pv_tc(float* __restrict__ outp)
{
    const int nt = blockIdx.x, mt = blockIdx.y, b = blockIdx.z;
    const int m0 = mt * 128, n0 = nt * 128;

    float acc[4][4][4];
    mma_gemm(g_P + (size_t)b * S * S + (size_t)m0 * S, S,
             g_Vt + (size_t)b * D * S + (size_t)n0 * S, S,
             (mt + 1) * 4, acc);

    float* O = outp + (size_t)b * S * D;
    const int warp = threadIdx.x >> 5, lane = threadIdx.x & 31;
    const int g = lane >> 2, tg = lane & 3;
    const int wm = (warp >> 2) * 64, wn = (warp & 3) * 32;
#pragma unroll
    for (int mi = 0; mi < 4; mi++) {
        int row0 = m0 + wm + mi * 16 + g;
        float inv0 = 1.f / g_sum[b * S + row0];
        float inv1 = 1.f / g_sum[b * S + row0 + 8];
#pragma unroll
        for (int ni = 0; ni < 4; ni++) {
            int col = n0 + wn + ni * 8 + 2 * tg;
            float2 v0 = {acc[mi][ni][0] * inv0, acc[mi][ni][1] * inv0};
            float2 v1 = {acc[mi][ni][2] * inv1, acc[mi][ni][3] * inv1};
            *(float2*)(O + (size_t)row0 * D + col) = v0;
            *(float2*)(O + (size_t)(row0 + 8) * D + col) = v1;
        }
    }
}

// ---------------------------------------------------------------------------
extern "C" void kernel_launch(void* const* d_in, const int* in_sizes, int n_in,
                              void* d_out, int out_size)
{
    const float* x  = (const float*)d_in[0];
    const float* wq = (const float*)d_in[1];
    const float* bq = (const float*)d_in[2];
    const float* wk = (const float*)d_in[3];
    const float* bk = (const float*)d_in[4];
    const float* wv = (const float*)d_in[5];
    const float* bv = (const float*)d_in[6];
    float* out = (float*)d_out;

    cudaFuncSetAttribute(qkv_tc,    cudaFuncAttributeMaxDynamicSharedMemorySize, SMEM_BYTES);
    cudaFuncSetAttribute(scores_tc, cudaFuncAttributeMaxDynamicSharedMemorySize, SMEM_BYTES);
    cudaFuncSetAttribute(pv_tc,     cudaFuncAttributeMaxDynamicSharedMemorySize, SMEM_BYTES);

    dim3 blk(256);

    // 1) pre-passes
    transpose_w<<<dim3(D / 32, E / 32, 3), blk>>>(wq, wk, wv);
    round_x<<<(size_t)M_TOT * E / (256 * 4), blk>>>(x);

    // 2) QKV projections (V written transposed, per-batch panes)
    qkv_tc<<<dim3(D / 128, M_TOT / 128, 3), blk, SMEM_BYTES>>>(bq, bk, bv);

    // 3) causal scores
    scores_tc<<<dim3(S / 128, S / 128, B), blk, SMEM_BYTES>>>();

    // 4) softmax
    softmax_w<<<dim3(S / 8, B), blk>>>();

    // 5) O = P @ V
    pv_tc<<<dim3(D / 128, S / 128, B), blk, SMEM_BYTES>>>(out);
}